// round 13
// baseline (speedup 1.0000x reference)
#include <cuda_runtime.h>
#include <cuda_bf16.h>
#include <math.h>

// ---------------- problem constants ----------------
#define NB 4096
#define ND 128
#define NT 32                  // 128-row tiles
#define NPAIR 528
#define INV_TEMP 14.285714285714285714f          // 1/0.07
#define KE 20.609929155556619f                   // INV_TEMP * log2(e)
#define LN2 0.69314718055994531f

// ---------------- device scratch (no allocs) ----------------
__device__ float g_Rp[2][8][NB];                  // partial row-max per pool tile
__device__ float g_RfM[NB];
__device__ float g_RsM[NB];
__device__ unsigned g_baseBits[32768];            // [256 rows][128 words]
__device__ float g_part[NT][NB * 6];              // [slot][row*6+q]
__device__ float g_sum[NB * 6];
__device__ __nv_bfloat16 g_bf[4][2][NB * ND];     // [stage][hi/lo][elem]
__device__ __nv_bfloat16 g_bfp[2][2][1024 * ND];  // pools [mat][hi/lo]

// ---------------- helpers ----------------
__device__ __forceinline__ float ex2f(float x) {
    float r; asm("ex2.approx.ftz.f32 %0, %1;" : "=f"(r) : "f"(x)); return r;
}
__device__ __forceinline__ float lg2f(float x) {
    float r; asm("lg2.approx.ftz.f32 %0, %1;" : "=f"(r) : "f"(x)); return r;
}
__device__ __forceinline__ unsigned smem_u32(const void* p) {
    return (unsigned)__cvta_generic_to_shared(p);
}

#define CP_ASYNC16(dst, src) asm volatile("cp.async.cg.shared.global [%0], [%1], 16;" :: "r"(dst), "l"(src))
#define CP_COMMIT() asm volatile("cp.async.commit_group;" ::: "memory")
#define CP_WAIT1() asm volatile("cp.async.wait_group 1;" ::: "memory")
#define CP_WAIT0() asm volatile("cp.async.wait_group 0;" ::: "memory")

__device__ __forceinline__ void ldsm4(unsigned& r0, unsigned& r1, unsigned& r2,
                                      unsigned& r3, unsigned addr) {
    asm volatile("ldmatrix.sync.aligned.m8n8.x4.shared.b16 {%0,%1,%2,%3}, [%4];"
                 : "=r"(r0), "=r"(r1), "=r"(r2), "=r"(r3) : "r"(addr));
}
__device__ __forceinline__ void mma_bf16(float* d, const unsigned* a, const unsigned* b) {
    asm volatile("mma.sync.aligned.m16n8k16.row.col.f32.bf16.bf16.f32 "
                 "{%0,%1,%2,%3}, {%4,%5,%6,%7}, {%8,%9}, {%0,%1,%2,%3};"
                 : "+f"(d[0]), "+f"(d[1]), "+f"(d[2]), "+f"(d[3])
                 : "r"(a[0]), "r"(a[1]), "r"(a[2]), "r"(a[3]),
                   "r"(b[0]), "r"(b[1]));
}

// Fragment-cached triple-combo k16 step over 8 n-pairs:
// 2 A-ldsm + 16 B-ldsm feed 48 MMAs (was 27 ldsm).
__device__ __forceinline__ void mma_k16_step(float* acc, unsigned ta_hi, unsigned ta_lo,
                                             unsigned tb_hi, unsigned tb_lo,
                                             unsigned aoff, unsigned boff, int ks) {
    unsigned ah[4], al[4];
    ldsm4(ah[0], ah[1], ah[2], ah[3], ta_hi + aoff + ks * 32);
    ldsm4(al[0], al[1], al[2], al[3], ta_lo + aoff + ks * 32);
#pragma unroll
    for (int np = 0; np < 8; np++) {
        unsigned bh[4], bl[4];
        ldsm4(bh[0], bh[1], bh[2], bh[3], tb_hi + np * 2304u + boff + ks * 32);
        ldsm4(bl[0], bl[1], bl[2], bl[3], tb_lo + np * 2304u + boff + ks * 32);
        float* d = acc + np * 8;
        mma_bf16(d,     ah, bh);
        mma_bf16(d + 4, ah, bh + 2);
        mma_bf16(d,     ah, bl);
        mma_bf16(d + 4, ah, bl + 2);
        mma_bf16(d,     al, bh);
        mma_bf16(d + 4, al, bh + 2);
    }
}

// ---------------- fused prep: split-bf16 conversions + mask pack ----------------
__global__ void prep_kernel(const float* __restrict__ z, const float* __restrict__ spr,
                            const float* __restrict__ f, const float* __restrict__ zmix,
                            const float* __restrict__ pag, const float* __restrict__ psp,
                            const float* __restrict__ base) {
    int i = blockIdx.x * 256 + threadIdx.x;     // 524288 threads
    const float* srcs[4] = {f, spr, z, zmix};
#pragma unroll
    for (int m = 0; m < 4; m++) {
        float x = srcs[m][i];
        __nv_bfloat16 hi = __float2bfloat16(x);
        __nv_bfloat16 lo = __float2bfloat16(x - __bfloat162float(hi));
        g_bf[m][0][i] = hi;
        g_bf[m][1][i] = lo;
    }
    if (i < 131072) {
        const float* ps[2] = {pag, psp};
#pragma unroll
        for (int m = 0; m < 2; m++) {
            float x = ps[m][i];
            __nv_bfloat16 hi = __float2bfloat16(x);
            __nv_bfloat16 lo = __float2bfloat16(x - __bfloat162float(hi));
            g_bfp[m][0][i] = hi;
            g_bfp[m][1][i] = lo;
        }
    }
    if (i < 32768) {
        const float* p = base + (size_t)i * 32;
        unsigned bits = 0;
#pragma unroll
        for (int b = 0; b < 32; b++) bits |= (p[b] > 0.f) ? (1u << b) : 0u;
        g_baseBits[i] = bits;
    }
}

// ---------------- shared tile loader ----------------
#define TILE_B 18432u          // 128 rows x 144B pitch
#define BUF_STRIDE 73728u      // 4 tiles

__device__ __forceinline__ void load_tile(unsigned sdst,
                                          const __nv_bfloat16* __restrict__ src,
                                          int row0, int h, int tid) {
#pragma unroll
    for (int i = 0; i < 4; i++) {
        int idx = tid + i * 256;
        int r = idx >> 3, cc = idx & 7;
        CP_ASYNC16(sdst + r * 144 + cc * 16,
                   src + (size_t)(row0 + r) * ND + h * 64 + cc * 8);
    }
}

// ---------------- rmax kernel: tensor path, pipelined chunks ----------------
__global__ void __launch_bounds__(256, 1)
rmax2_kernel() {
    extern __shared__ char smc[];
    unsigned sb = smem_u32(smc);
    int tid = threadIdx.x;
    int w = tid >> 5, l = tid & 31;
    int g0 = blockIdx.x * 128, p0 = blockIdx.y * 128, mat = blockIdx.z;
    int rA = 16 * w + (l >> 2), rB = rA + 8;

    const __nv_bfloat16* Ahi = &g_bf[mat][0][0];
    const __nv_bfloat16* Alo = &g_bf[mat][1][0];
    const __nv_bfloat16* Bhi = &g_bfp[mat][0][0];
    const __nv_bfloat16* Blo = &g_bfp[mat][1][0];

#pragma unroll
    for (int c = 0; c < 2; c++) {
        unsigned bs = sb + c * BUF_STRIDE;
        load_tile(bs,              Ahi, g0, c, tid);
        load_tile(bs + TILE_B,     Alo, g0, c, tid);
        load_tile(bs + 2 * TILE_B, Bhi, p0, c, tid);
        load_tile(bs + 3 * TILE_B, Blo, p0, c, tid);
        CP_COMMIT();
    }

    unsigned aoff = (unsigned)((16 * w + (l & 15)) * 144 + ((l & 16) ? 16 : 0));
    unsigned boff = (unsigned)(((l & 7) + ((l & 16) ? 8 : 0)) * 144 + ((l & 8) ? 16 : 0));

    float acc[64];
#pragma unroll
    for (int i = 0; i < 64; i++) acc[i] = 0.f;
#pragma unroll
    for (int c = 0; c < 2; c++) {
        if (c == 0) { CP_WAIT1(); } else { CP_WAIT0(); }
        __syncthreads();
        unsigned bufb = sb + (unsigned)c * BUF_STRIDE;
#pragma unroll
        for (int ks = 0; ks < 4; ks++)
            mma_k16_step(acc, bufb, bufb + TILE_B,
                         bufb + 2 * TILE_B, bufb + 3 * TILE_B, aoff, boff, ks);
    }

    float mxA = -1e30f, mxB = -1e30f;
#pragma unroll
    for (int t2 = 0; t2 < 16; t2++) {
        mxA = fmaxf(mxA, fmaxf(acc[t2 * 4], acc[t2 * 4 + 1]));
        mxB = fmaxf(mxB, fmaxf(acc[t2 * 4 + 2], acc[t2 * 4 + 3]));
    }
#pragma unroll
    for (int off = 1; off < 4; off <<= 1) {
        mxA = fmaxf(mxA, __shfl_xor_sync(0xffffffffu, mxA, off));
        mxB = fmaxf(mxB, __shfl_xor_sync(0xffffffffu, mxB, off));
    }
    if ((l & 3) == 0) {
        g_Rp[mat][blockIdx.y][g0 + rA] = mxA;
        g_Rp[mat][blockIdx.y][g0 + rB] = mxB;
    }
}

__global__ void merge2_kernel() {
    int i = blockIdx.x * 256 + threadIdx.x;
    float mf = -1e30f, ms = -1e30f;
#pragma unroll
    for (int p = 0; p < 8; p++) {
        mf = fmaxf(mf, g_Rp[0][p][i]);
        ms = fmaxf(ms, g_Rp[1][p][i]);
    }
    g_RfM[i] = mf;
    g_RsM[i] = ms;
}

// ---------------- pair kernel: symmetric, mma.sync ----------------
#define OFF_COLR 147456
#define OFF_BB   148480
#define OFF_TB   150528
#define OFF_CSUM 152576        // [8 warps][6 q][128 cols] floats = 24576 B
#define SMEM_PAIR 177152

__global__ void __launch_bounds__(256, 1)
pair_kernel() {
    extern __shared__ char smc[];
    unsigned sb = smem_u32(smc);
    float* smf = (float*)smc;
    float* colRf = smf + OFF_COLR / 4;
    float* colRs = colRf + 128;
    unsigned* bbr = (unsigned*)(smc + OFF_BB);
    unsigned* tbt = (unsigned*)(smc + OFF_TB);
    float* csum = smf + OFF_CSUM / 4;

    int tid = threadIdx.x;
    int w = tid >> 5, l = tid & 31;

    int pi = blockIdx.x, a = 0;
    while (pi >= NT - a) { pi -= NT - a; a++; }
    int b = a + pi;
    int g0 = a * 128, j0 = b * 128;

    int rA = 16 * w + (l >> 2), rB = rA + 8;

    if (tid < 128) {
        colRf[tid] = g_RfM[j0 + tid];
        colRs[tid] = g_RsM[j0 + tid];
        const unsigned* srcR = &g_baseBits[((g0 + tid) & 255) * 128 + (j0 >> 5)];
        const unsigned* srcT = &g_baseBits[((j0 + tid) & 255) * 128 + (g0 >> 5)];
#pragma unroll
        for (int q = 0; q < 4; q++) {
            bbr[tid * 4 + q] = srcR[q];
            tbt[tid * 4 + q] = srcT[q];
        }
    }

    // prologue: chunks 0,1 of stage f
    {
        unsigned b0 = sb;
        load_tile(b0,              &g_bf[0][0][0], g0, 0, tid);
        load_tile(b0 + TILE_B,     &g_bf[0][1][0], g0, 0, tid);
        load_tile(b0 + 2 * TILE_B, &g_bf[0][0][0], j0, 0, tid);
        load_tile(b0 + 3 * TILE_B, &g_bf[0][1][0], j0, 0, tid);
        CP_COMMIT();
        unsigned b1 = sb + BUF_STRIDE;
        load_tile(b1,              &g_bf[0][0][0], g0, 1, tid);
        load_tile(b1 + TILE_B,     &g_bf[0][1][0], g0, 1, tid);
        load_tile(b1 + 2 * TILE_B, &g_bf[0][0][0], j0, 1, tid);
        load_tile(b1 + 3 * TILE_B, &g_bf[0][1][0], j0, 1, tid);
        CP_COMMIT();
    }

    unsigned aoff = (unsigned)((16 * w + (l & 15)) * 144 + ((l & 16) ? 16 : 0));
    unsigned boff = (unsigned)(((l & 7) + ((l & 16) ? 8 : 0)) * 144 + ((l & 8) ? 16 : 0));

    float RfA = g_RfM[g0 + rA], RfB = g_RfM[g0 + rB];
    float RsA = g_RsM[g0 + rA], RsB = g_RsM[g0 + rB];

    unsigned long long keep = ~0ull;
    if (a == b) {
#pragma unroll
        for (int t2 = 0; t2 < 16; t2++)
#pragma unroll
            for (int j = 0; j < 4; j++) {
                int col = 8 * t2 + 2 * (l & 3) + (j & 1);
                int row = rA + ((j & 2) ? 8 : 0);
                if (col == row) keep &= ~(1ull << (t2 * 4 + j));
            }
    }

    float acc[64];
    unsigned long long bA = 0, bE = 0, bN = 0, bNT = 0;
    float SzA = 0.f, SzB = 0.f, ZzA = 0.f, ZzB = 0.f;
    float SmA = 0.f, SmB = 0.f, ZmA = 0.f, ZmB = 0.f;

    for (int c = 0; c < 8; c++) {
        if (c < 7) { CP_WAIT1(); } else { CP_WAIT0(); }
        __syncthreads();
        if ((c & 1) == 0) {
#pragma unroll
            for (int i = 0; i < 64; i++) acc[i] = 0.f;
        }
        unsigned bufb = sb + (unsigned)(c & 1) * BUF_STRIDE;
#pragma unroll
        for (int ks = 0; ks < 4; ks++)
            mma_k16_step(acc, bufb, bufb + TILE_B,
                         bufb + 2 * TILE_B, bufb + 3 * TILE_B, aoff, boff, ks);

        if (c == 1) {
            // ---- f masks: bA, bN, bNT ----
            unsigned wA4[4], wB4[4];
#pragma unroll
            for (int q = 0; q < 4; q++) { wA4[q] = bbr[rA * 4 + q]; wB4[q] = bbr[rB * 4 + q]; }
            unsigned long long m1 = 0, ng = 0, ngT = 0;
#pragma unroll
            for (int t2 = 0; t2 < 16; t2++)
#pragma unroll
                for (int j = 0; j < 4; j++) {
                    int idx = t2 * 4 + j;
                    float v = acc[idx];
                    int col = 8 * t2 + 2 * (l & 3) + (j & 1);
                    float Rr = (j & 2) ? RfB : RfA;
                    if ((Rr < v) | (colRf[col] < v)) m1 |= 1ull << idx;
                    unsigned word = (j & 2) ? wB4[col >> 5] : wA4[col >> 5];
                    if ((word >> (col & 31)) & 1u) ng |= 1ull << idx;
                    int rr = (j & 2) ? rB : rA;
                    if ((tbt[col * 4 + (rr >> 5)] >> (rr & 31)) & 1u) ngT |= 1ull << idx;
                }
            bA = m1 & keep;
            bN = bA | (ng & keep);
            bNT = bA | (ngT & keep);
        } else if (c == 3) {
            // ---- s masks: bE; then col-side counts ----
            unsigned long long m2 = 0;
#pragma unroll
            for (int t2 = 0; t2 < 16; t2++)
#pragma unroll
                for (int j = 0; j < 4; j++) {
                    int idx = t2 * 4 + j;
                    float v = acc[idx];
                    int col = 8 * t2 + 2 * (l & 3) + (j & 1);
                    float Rr = (j & 2) ? RsB : RsA;
                    if ((Rr < v) | (colRs[col] < v)) m2 |= 1ull << idx;
                }
            bE = m2 & keep;
            if (a != b) {
#pragma unroll
                for (int jb = 0; jb < 2; jb++) {
                    float cw[16], cv[16];
#pragma unroll
                    for (int t2 = 0; t2 < 16; t2++) {
                        float s1 = 0.f, s2 = 0.f;
#pragma unroll
                        for (int j2 = 0; j2 < 2; j2++) {
                            int idx = t2 * 4 + jb + 2 * j2;
                            float wA = ((bA >> idx) & 1ull) ? 1.0f : 0.0f;
                            float wE = ((bE >> idx) & 1ull) ? 0.5f : 0.0f;
                            s1 += wA + wE; s2 += wA;
                        }
                        cw[t2] = s1; cv[t2] = s2;
                    }
#pragma unroll
                    for (int off = 4; off < 32; off <<= 1)
#pragma unroll
                        for (int t2 = 0; t2 < 16; t2++) {
                            cw[t2] += __shfl_xor_sync(0xffffffffu, cw[t2], off);
                            cv[t2] += __shfl_xor_sync(0xffffffffu, cv[t2], off);
                        }
                    if (l < 4) {
#pragma unroll
                        for (int t2 = 0; t2 < 16; t2++) {
                            int col = 8 * t2 + 2 * l + jb;
                            csum[w * 768 + 4 * 128 + col] = cw[t2];
                            csum[w * 768 + 5 * 128 + col] = cv[t2];
                        }
                    }
                }
            }
        } else if (c == 5 || c == 7) {
            // ---- logit epilogue: row side ----
            float sA = 0.f, sB = 0.f, zA = 0.f, zB = 0.f;
#pragma unroll
            for (int t2 = 0; t2 < 16; t2++)
#pragma unroll
                for (int j = 0; j < 4; j++) {
                    int idx = t2 * 4 + j;
                    float v = acc[idx];
                    float wgt = (((bA >> idx) & 1ull) ? 1.0f : 0.0f) +
                                (((bE >> idx) & 1ull) ? 0.5f : 0.0f);
                    float e = ex2f(KE * (v - 1.0f));
                    float za = ((bN >> idx) & 1ull) ? e : 0.f;
                    if (j & 2) { sB += wgt * v; zB += za; }
                    else       { sA += wgt * v; zA += za; }
                }
            if (c == 5) { SzA = sA; SzB = sB; ZzA = zA; ZzB = zB; }
            else        { SmA = sA; SmB = sB; ZmA = zA; ZmB = zB; }
            // ---- col side ----
            if (a != b) {
                int q0 = (c == 5) ? 0 : 2;
#pragma unroll
                for (int jb = 0; jb < 2; jb++) {
                    float cz[16], cs[16];
#pragma unroll
                    for (int t2 = 0; t2 < 16; t2++) {
                        float sv = 0.f, ze = 0.f;
#pragma unroll
                        for (int j2 = 0; j2 < 2; j2++) {
                            int idx = t2 * 4 + jb + 2 * j2;
                            float v = acc[idx];
                            float wgt = (((bA >> idx) & 1ull) ? 1.0f : 0.0f) +
                                        (((bE >> idx) & 1ull) ? 0.5f : 0.0f);
                            sv += wgt * v;
                            float e = ex2f(KE * (v - 1.0f));
                            ze += ((bNT >> idx) & 1ull) ? e : 0.f;
                        }
                        cs[t2] = sv; cz[t2] = ze;
                    }
#pragma unroll
                    for (int off = 4; off < 32; off <<= 1)
#pragma unroll
                        for (int t2 = 0; t2 < 16; t2++) {
                            cs[t2] += __shfl_xor_sync(0xffffffffu, cs[t2], off);
                            cz[t2] += __shfl_xor_sync(0xffffffffu, cz[t2], off);
                        }
                    if (l < 4) {
#pragma unroll
                        for (int t2 = 0; t2 < 16; t2++) {
                            int col = 8 * t2 + 2 * l + jb;
                            csum[w * 768 + q0 * 128 + col] = cz[t2];
                            csum[w * 768 + (q0 + 1) * 128 + col] = cs[t2];
                        }
                    }
                }
            }
        }

        __syncthreads();
        if (c + 2 < 8) {
            int cc = c + 2;
            const __nv_bfloat16* hi = &g_bf[cc >> 1][0][0];
            const __nv_bfloat16* lo = &g_bf[cc >> 1][1][0];
            int h = cc & 1;
            unsigned bn = sb + (unsigned)(c & 1) * BUF_STRIDE;
            load_tile(bn,              hi, g0, h, tid);
            load_tile(bn + TILE_B,     lo, g0, h, tid);
            load_tile(bn + 2 * TILE_B, hi, j0, h, tid);
            load_tile(bn + 3 * TILE_B, lo, j0, h, tid);
            CP_COMMIT();
        }
    }

    // ---- row-side write ----
    float pAa = (float)__popcll(bA & 0x3333333333333333ULL);
    float pAb = (float)__popcll(bA & 0xCCCCCCCCCCCCCCCCULL);
    float pEa = (float)__popcll(bE & 0x3333333333333333ULL);
    float pEb = (float)__popcll(bE & 0xCCCCCCCCCCCCCCCCULL);
    float qA[6] = {ZzA, ZmA, SzA, SmA, pAa + 0.5f * pEa, pAa};
    float qB[6] = {ZzB, ZmB, SzB, SmB, pAb + 0.5f * pEb, pAb};
#pragma unroll
    for (int q = 0; q < 6; q++) {
#pragma unroll
        for (int off = 1; off < 4; off <<= 1) {
            qA[q] += __shfl_xor_sync(0xffffffffu, qA[q], off);
            qB[q] += __shfl_xor_sync(0xffffffffu, qB[q], off);
        }
    }
    if ((l & 3) == 0) {
        float* dA = &g_part[b][(size_t)(g0 + rA) * 6];
        float* dB = &g_part[b][(size_t)(g0 + rB) * 6];
#pragma unroll
        for (int q = 0; q < 6; q++) { dA[q] = qA[q]; dB[q] = qB[q]; }
    }

    // ---- col-side write ----
    __syncthreads();
    if (a != b && tid < 128) {
        float s[6] = {0.f, 0.f, 0.f, 0.f, 0.f, 0.f};
#pragma unroll
        for (int w8 = 0; w8 < 8; w8++)
#pragma unroll
            for (int q = 0; q < 6; q++) s[q] += csum[w8 * 768 + q * 128 + tid];
        float* d = &g_part[a][(size_t)(j0 + tid) * 6];
        d[0] = s[0];   // Zz
        d[1] = s[2];   // Zm
        d[2] = s[1];   // Sz
        d[3] = s[3];   // Sm
        d[4] = s[4];   // ws
        d[5] = s[5];   // vc
    }
}

// ---------------- slot sum + final reduction ----------------
__global__ void slotsum_kernel() {
    int i = blockIdx.x * 256 + threadIdx.x;
    float s = 0.f;
    for (int sl = 0; sl < NT; sl++) s += g_part[sl][i];
    g_sum[i] = s;
}

__global__ void reduce_kernel(float* __restrict__ out) {
    __shared__ float s1[256], s2[256];
    int tid = threadIdx.x;
    float grand = 0.f;
    for (int m = 0; m < 16; m++) {
        int i = m * 256 + tid;
        float q[6];
#pragma unroll
        for (int qn = 0; qn < 6; qn++) q[qn] = g_sum[(size_t)i * 6 + qn];
        float Zz = q[0], Zm = q[1], Sz = q[2], Sm = q[3], ww = q[4], vcc = q[5];
        float num = 0.f, den = 0.f;
        if (vcc > 0.5f) {
            float lzz = INV_TEMP + LN2 * lg2f(Zz);
            float lzm = INV_TEMP + LN2 * lg2f(Zm);
            num = INV_TEMP * (Sz + Sm) - ww * (lzz + lzm);
            den = ww;
        }
        s1[tid] = num;
        s2[tid] = den;
        __syncthreads();
        for (int off = 128; off > 0; off >>= 1) {
            if (tid < off) { s1[tid] += s1[tid + off]; s2[tid] += s2[tid + off]; }
            __syncthreads();
        }
        if (tid == 0 && s2[0] != 0.f) grand += s1[0] / s2[0];
        __syncthreads();
    }
    if (tid == 0) out[0] = -grand / 32.0f;   // /M/2 with M=16
}

// ---------------- launch ----------------
extern "C" void kernel_launch(void* const* d_in, const int* in_sizes, int n_in,
                              void* d_out, int out_size) {
    const float* z    = (const float*)d_in[0];
    const float* spr  = (const float*)d_in[1];
    const float* f    = (const float*)d_in[2];
    const float* pag  = (const float*)d_in[3];
    const float* psp  = (const float*)d_in[4];
    const float* zmix = (const float*)d_in[5];
    const float* base = (const float*)d_in[6];
    float* out = (float*)d_out;

    const int SMEM_RMAX = 2 * BUF_STRIDE;     // 147456
    cudaFuncSetAttribute(rmax2_kernel, cudaFuncAttributeMaxDynamicSharedMemorySize, SMEM_RMAX);
    cudaFuncSetAttribute(pair_kernel, cudaFuncAttributeMaxDynamicSharedMemorySize, SMEM_PAIR);

    prep_kernel<<<2048, 256>>>(z, spr, f, zmix, pag, psp, base);
    rmax2_kernel<<<dim3(32, 8, 2), 256, SMEM_RMAX>>>();
    merge2_kernel<<<16, 256>>>();
    pair_kernel<<<NPAIR, 256, SMEM_PAIR>>>();
    slotsum_kernel<<<96, 256>>>();
    reduce_kernel<<<1, 256>>>(out);
}

// round 14
// speedup vs baseline: 1.0612x; 1.0612x over previous
#include <cuda_runtime.h>
#include <cuda_bf16.h>
#include <math.h>

// ---------------- problem constants ----------------
#define NB 4096
#define ND 128
#define NT 32                  // 128-row tiles
#define NPAIR 528
#define INV_TEMP 14.285714285714285714f          // 1/0.07
#define KE 20.609929155556619f                   // INV_TEMP * log2(e)
#define LN2 0.69314718055994531f

// ---------------- device scratch (no allocs) ----------------
__device__ float g_Rp[2][8][NB];                  // partial row-max per pool tile
__device__ float g_RfM[NB];
__device__ float g_RsM[NB];
__device__ unsigned g_baseBits[32768];            // [256 rows][128 words]
__device__ float g_part[NT][NB * 6];              // [slot][row*6+q]
__device__ float g_sum[NB * 6];
__device__ __nv_bfloat16 g_bf[4][2][NB * ND];     // [stage][hi/lo][elem]
__device__ __nv_bfloat16 g_bfp[2][2][1024 * ND];  // pools [mat][hi/lo]

// ---------------- helpers ----------------
__device__ __forceinline__ float ex2f(float x) {
    float r; asm("ex2.approx.ftz.f32 %0, %1;" : "=f"(r) : "f"(x)); return r;
}
__device__ __forceinline__ float lg2f(float x) {
    float r; asm("lg2.approx.ftz.f32 %0, %1;" : "=f"(r) : "f"(x)); return r;
}
__device__ __forceinline__ unsigned smem_u32(const void* p) {
    return (unsigned)__cvta_generic_to_shared(p);
}

#define CP_ASYNC16(dst, src) asm volatile("cp.async.cg.shared.global [%0], [%1], 16;" :: "r"(dst), "l"(src))
#define CP_COMMIT() asm volatile("cp.async.commit_group;" ::: "memory")
#define CP_WAIT1() asm volatile("cp.async.wait_group 1;" ::: "memory")
#define CP_WAIT0() asm volatile("cp.async.wait_group 0;" ::: "memory")

__device__ __forceinline__ void ldsm4(unsigned& r0, unsigned& r1, unsigned& r2,
                                      unsigned& r3, unsigned addr) {
    asm volatile("ldmatrix.sync.aligned.m8n8.x4.shared.b16 {%0,%1,%2,%3}, [%4];"
                 : "=r"(r0), "=r"(r1), "=r"(r2), "=r"(r3) : "r"(addr));
}
__device__ __forceinline__ void mma_bf16(float* d, const unsigned* a, const unsigned* b) {
    asm volatile("mma.sync.aligned.m16n8k16.row.col.f32.bf16.bf16.f32 "
                 "{%0,%1,%2,%3}, {%4,%5,%6,%7}, {%8,%9}, {%0,%1,%2,%3};"
                 : "+f"(d[0]), "+f"(d[1]), "+f"(d[2]), "+f"(d[3])
                 : "r"(a[0]), "r"(a[1]), "r"(a[2]), "r"(a[3]),
                   "r"(b[0]), "r"(b[1]));
}

// ---------------- fused prep: split-bf16 conversions + mask pack ----------------
__global__ void prep_kernel(const float* __restrict__ z, const float* __restrict__ spr,
                            const float* __restrict__ f, const float* __restrict__ zmix,
                            const float* __restrict__ pag, const float* __restrict__ psp,
                            const float* __restrict__ base) {
    int i = blockIdx.x * 256 + threadIdx.x;     // 524288 threads
    const float* srcs[4] = {f, spr, z, zmix};
#pragma unroll
    for (int m = 0; m < 4; m++) {
        float x = srcs[m][i];
        __nv_bfloat16 hi = __float2bfloat16(x);
        __nv_bfloat16 lo = __float2bfloat16(x - __bfloat162float(hi));
        g_bf[m][0][i] = hi;
        g_bf[m][1][i] = lo;
    }
    if (i < 131072) {
        const float* ps[2] = {pag, psp};
#pragma unroll
        for (int m = 0; m < 2; m++) {
            float x = ps[m][i];
            __nv_bfloat16 hi = __float2bfloat16(x);
            __nv_bfloat16 lo = __float2bfloat16(x - __bfloat162float(hi));
            g_bfp[m][0][i] = hi;
            g_bfp[m][1][i] = lo;
        }
    }
    if (i < 32768) {
        const float* p = base + (size_t)i * 32;
        unsigned bits = 0;
#pragma unroll
        for (int b = 0; b < 32; b++) bits |= (p[b] > 0.f) ? (1u << b) : 0u;
        g_baseBits[i] = bits;
    }
}

// ---------------- shared tile loader ----------------
#define TILE_B 18432u          // 128 rows x 144B pitch
#define BUF_STRIDE 73728u      // 4 tiles

__device__ __forceinline__ void load_tile(unsigned sdst,
                                          const __nv_bfloat16* __restrict__ src,
                                          int row0, int h, int tid, int nthr) {
#pragma unroll
    for (int idx = tid; idx < 1024; idx += nthr) {
        int r = idx >> 3, cc = idx & 7;
        CP_ASYNC16(sdst + r * 144 + cc * 16,
                   src + (size_t)(row0 + r) * ND + h * 64 + cc * 8);
    }
}

// ---------------- rmax kernel: tensor path (proven round-13 code) ----------------
__device__ __forceinline__ void mma_k16_step8(float* acc, unsigned ta_hi, unsigned ta_lo,
                                              unsigned tb_hi, unsigned tb_lo,
                                              unsigned aoff, unsigned boff, int ks) {
    unsigned ah[4], al[4];
    ldsm4(ah[0], ah[1], ah[2], ah[3], ta_hi + aoff + ks * 32);
    ldsm4(al[0], al[1], al[2], al[3], ta_lo + aoff + ks * 32);
#pragma unroll
    for (int np = 0; np < 8; np++) {
        unsigned bh[4], bl[4];
        ldsm4(bh[0], bh[1], bh[2], bh[3], tb_hi + np * 2304u + boff + ks * 32);
        ldsm4(bl[0], bl[1], bl[2], bl[3], tb_lo + np * 2304u + boff + ks * 32);
        float* d = acc + np * 8;
        mma_bf16(d,     ah, bh);
        mma_bf16(d + 4, ah, bh + 2);
        mma_bf16(d,     ah, bl);
        mma_bf16(d + 4, ah, bl + 2);
        mma_bf16(d,     al, bh);
        mma_bf16(d + 4, al, bh + 2);
    }
}

__global__ void __launch_bounds__(256, 1)
rmax2_kernel() {
    extern __shared__ char smc[];
    unsigned sb = smem_u32(smc);
    int tid = threadIdx.x;
    int w = tid >> 5, l = tid & 31;
    int g0 = blockIdx.x * 128, p0 = blockIdx.y * 128, mat = blockIdx.z;
    int rA = 16 * w + (l >> 2), rB = rA + 8;

    const __nv_bfloat16* Ahi = &g_bf[mat][0][0];
    const __nv_bfloat16* Alo = &g_bf[mat][1][0];
    const __nv_bfloat16* Bhi = &g_bfp[mat][0][0];
    const __nv_bfloat16* Blo = &g_bfp[mat][1][0];

#pragma unroll
    for (int c = 0; c < 2; c++) {
        unsigned bs = sb + c * BUF_STRIDE;
        load_tile(bs,              Ahi, g0, c, tid, 256);
        load_tile(bs + TILE_B,     Alo, g0, c, tid, 256);
        load_tile(bs + 2 * TILE_B, Bhi, p0, c, tid, 256);
        load_tile(bs + 3 * TILE_B, Blo, p0, c, tid, 256);
        CP_COMMIT();
    }

    unsigned aoff = (unsigned)((16 * w + (l & 15)) * 144 + ((l & 16) ? 16 : 0));
    unsigned boff = (unsigned)(((l & 7) + ((l & 16) ? 8 : 0)) * 144 + ((l & 8) ? 16 : 0));

    float acc[64];
#pragma unroll
    for (int i = 0; i < 64; i++) acc[i] = 0.f;
#pragma unroll
    for (int c = 0; c < 2; c++) {
        if (c == 0) { CP_WAIT1(); } else { CP_WAIT0(); }
        __syncthreads();
        unsigned bufb = sb + (unsigned)c * BUF_STRIDE;
#pragma unroll
        for (int ks = 0; ks < 4; ks++)
            mma_k16_step8(acc, bufb, bufb + TILE_B,
                          bufb + 2 * TILE_B, bufb + 3 * TILE_B, aoff, boff, ks);
    }

    float mxA = -1e30f, mxB = -1e30f;
#pragma unroll
    for (int t2 = 0; t2 < 16; t2++) {
        mxA = fmaxf(mxA, fmaxf(acc[t2 * 4], acc[t2 * 4 + 1]));
        mxB = fmaxf(mxB, fmaxf(acc[t2 * 4 + 2], acc[t2 * 4 + 3]));
    }
#pragma unroll
    for (int off = 1; off < 4; off <<= 1) {
        mxA = fmaxf(mxA, __shfl_xor_sync(0xffffffffu, mxA, off));
        mxB = fmaxf(mxB, __shfl_xor_sync(0xffffffffu, mxB, off));
    }
    if ((l & 3) == 0) {
        g_Rp[mat][blockIdx.y][g0 + rA] = mxA;
        g_Rp[mat][blockIdx.y][g0 + rB] = mxB;
    }
}

__global__ void merge2_kernel() {
    int i = blockIdx.x * 256 + threadIdx.x;
    float mf = -1e30f, ms = -1e30f;
#pragma unroll
    for (int p = 0; p < 8; p++) {
        mf = fmaxf(mf, g_Rp[0][p][i]);
        ms = fmaxf(ms, g_Rp[1][p][i]);
    }
    g_RfM[i] = mf;
    g_RsM[i] = ms;
}

// ---------------- pair kernel: symmetric, mma.sync, 512 threads ----------------
// 16 warps; warp (wr = w>>1, wc = w&1) owns rows 16wr..16wr+15 x cols 64wc..64wc+63.
// acc[32] per thread (4 n-pairs x 8), masks are u32.
#define OFF_COLR 147456        // 256 floats
#define OFF_BB   148480        // 512 u32
#define OFF_TB   150528        // 512 u32
#define OFF_CSUM 152576        // [8 wr][6 q][128 cols] = 24576 B
#define OFF_RSUM 177152        // [2 wc][128 rows][6] = 6144 B
#define SMEM_PAIR 183296

__device__ __forceinline__ void mma_k16_step4(float* acc, unsigned ta_hi, unsigned ta_lo,
                                              unsigned tb_hi, unsigned tb_lo,
                                              unsigned aoff, unsigned boff, int ks) {
    unsigned ah[4], al[4];
    ldsm4(ah[0], ah[1], ah[2], ah[3], ta_hi + aoff + ks * 32);
    ldsm4(al[0], al[1], al[2], al[3], ta_lo + aoff + ks * 32);
#pragma unroll
    for (int np = 0; np < 4; np++) {
        unsigned bh[4], bl[4];
        ldsm4(bh[0], bh[1], bh[2], bh[3], tb_hi + np * 2304u + boff + ks * 32);
        ldsm4(bl[0], bl[1], bl[2], bl[3], tb_lo + np * 2304u + boff + ks * 32);
        float* d = acc + np * 8;
        mma_bf16(d,     ah, bh);
        mma_bf16(d + 4, ah, bh + 2);
        mma_bf16(d,     ah, bl);
        mma_bf16(d + 4, ah, bl + 2);
        mma_bf16(d,     al, bh);
        mma_bf16(d + 4, al, bh + 2);
    }
}

__global__ void __launch_bounds__(512, 1)
pair_kernel() {
    extern __shared__ char smc[];
    unsigned sb = smem_u32(smc);
    float* smf = (float*)smc;
    float* colRf = smf + OFF_COLR / 4;
    float* colRs = colRf + 128;
    unsigned* bbr = (unsigned*)(smc + OFF_BB);
    unsigned* tbt = (unsigned*)(smc + OFF_TB);
    float* csum = smf + OFF_CSUM / 4;
    float* rsum = smf + OFF_RSUM / 4;

    int tid = threadIdx.x;
    int w = tid >> 5, l = tid & 31;
    int wr = w >> 1, wc = w & 1;
    int cb = wc * 64;

    int pi = blockIdx.x, a = 0;
    while (pi >= NT - a) { pi -= NT - a; a++; }
    int b = a + pi;
    int g0 = a * 128, j0 = b * 128;

    int rA = 16 * wr + (l >> 2), rB = rA + 8;

    if (tid < 128) {
        colRf[tid] = g_RfM[j0 + tid];
        colRs[tid] = g_RsM[j0 + tid];
        const unsigned* srcR = &g_baseBits[((g0 + tid) & 255) * 128 + (j0 >> 5)];
        const unsigned* srcT = &g_baseBits[((j0 + tid) & 255) * 128 + (g0 >> 5)];
#pragma unroll
        for (int q = 0; q < 4; q++) {
            bbr[tid * 4 + q] = srcR[q];
            tbt[tid * 4 + q] = srcT[q];
        }
    }

    // prologue: chunks 0,1 of stage f
    {
        unsigned b0 = sb;
        load_tile(b0,              &g_bf[0][0][0], g0, 0, tid, 512);
        load_tile(b0 + TILE_B,     &g_bf[0][1][0], g0, 0, tid, 512);
        load_tile(b0 + 2 * TILE_B, &g_bf[0][0][0], j0, 0, tid, 512);
        load_tile(b0 + 3 * TILE_B, &g_bf[0][1][0], j0, 0, tid, 512);
        CP_COMMIT();
        unsigned b1 = sb + BUF_STRIDE;
        load_tile(b1,              &g_bf[0][0][0], g0, 1, tid, 512);
        load_tile(b1 + TILE_B,     &g_bf[0][1][0], g0, 1, tid, 512);
        load_tile(b1 + 2 * TILE_B, &g_bf[0][0][0], j0, 1, tid, 512);
        load_tile(b1 + 3 * TILE_B, &g_bf[0][1][0], j0, 1, tid, 512);
        CP_COMMIT();
    }

    unsigned aoff = (unsigned)((16 * wr + (l & 15)) * 144 + ((l & 16) ? 16 : 0));
    unsigned boff = (unsigned)(cb * 144 + ((l & 7) + ((l & 16) ? 8 : 0)) * 144 +
                               ((l & 8) ? 16 : 0));

    float RfA = g_RfM[g0 + rA], RfB = g_RfM[g0 + rB];
    float RsA = g_RsM[g0 + rA], RsB = g_RsM[g0 + rB];

    unsigned keep = ~0u;
    if (a == b) {
#pragma unroll
        for (int np = 0; np < 4; np++)
#pragma unroll
            for (int j = 0; j < 8; j++) {
                int col = cb + np * 16 + ((j & 4) ? 8 : 0) + 2 * (l & 3) + (j & 1);
                int row = (j & 2) ? rB : rA;
                if (col == row) keep &= ~(1u << (np * 8 + j));
            }
    }

    float acc[32];
    unsigned bA = 0, bE = 0, bN = 0, bNT = 0;
    float SzA = 0.f, SzB = 0.f, ZzA = 0.f, ZzB = 0.f;
    float SmA = 0.f, SmB = 0.f, ZmA = 0.f, ZmB = 0.f;

    for (int c = 0; c < 8; c++) {
        if (c < 7) { CP_WAIT1(); } else { CP_WAIT0(); }
        __syncthreads();
        if ((c & 1) == 0) {
#pragma unroll
            for (int i = 0; i < 32; i++) acc[i] = 0.f;
        }
        unsigned bufb = sb + (unsigned)(c & 1) * BUF_STRIDE;
#pragma unroll
        for (int ks = 0; ks < 4; ks++)
            mma_k16_step4(acc, bufb, bufb + TILE_B,
                          bufb + 2 * TILE_B, bufb + 3 * TILE_B, aoff, boff, ks);

        if (c == 1) {
            // ---- f masks: bA, bN, bNT ----
            unsigned wA4[4], wB4[4];
#pragma unroll
            for (int q = 0; q < 4; q++) { wA4[q] = bbr[rA * 4 + q]; wB4[q] = bbr[rB * 4 + q]; }
            unsigned m1 = 0, ng = 0, ngT = 0;
#pragma unroll
            for (int np = 0; np < 4; np++)
#pragma unroll
                for (int j = 0; j < 8; j++) {
                    int idx = np * 8 + j;
                    float v = acc[idx];
                    int col = cb + np * 16 + ((j & 4) ? 8 : 0) + 2 * (l & 3) + (j & 1);
                    float Rr = (j & 2) ? RfB : RfA;
                    if ((Rr < v) | (colRf[col] < v)) m1 |= 1u << idx;
                    unsigned word = (j & 2) ? wB4[col >> 5] : wA4[col >> 5];
                    if ((word >> (col & 31)) & 1u) ng |= 1u << idx;
                    int rr = (j & 2) ? rB : rA;
                    if ((tbt[col * 4 + (rr >> 5)] >> (rr & 31)) & 1u) ngT |= 1u << idx;
                }
            bA = m1 & keep;
            bN = bA | (ng & keep);
            bNT = bA | (ngT & keep);
        } else if (c == 3) {
            // ---- s masks: bE ----
            unsigned m2 = 0;
#pragma unroll
            for (int np = 0; np < 4; np++)
#pragma unroll
                for (int j = 0; j < 8; j++) {
                    int idx = np * 8 + j;
                    float v = acc[idx];
                    int col = cb + np * 16 + ((j & 4) ? 8 : 0) + 2 * (l & 3) + (j & 1);
                    float Rr = (j & 2) ? RsB : RsA;
                    if ((Rr < v) | (colRs[col] < v)) m2 |= 1u << idx;
                }
            bE = m2 & keep;
            // ---- col-side counts (sum over the 2 rows of this thread) ----
            if (a != b) {
#pragma unroll
                for (int np = 0; np < 4; np++)
#pragma unroll
                    for (int jc = 0; jc < 4; jc++) {
                        int j0i = (jc & 1) | ((jc & 2) << 1);   // 0,1,4,5
                        int i1 = np * 8 + j0i, i2 = i1 + 2;
                        float wAs = (((bA >> i1) & 1u) ? 1.f : 0.f) +
                                    (((bA >> i2) & 1u) ? 1.f : 0.f);
                        float wEs = (((bE >> i1) & 1u) ? 1.f : 0.f) +
                                    (((bE >> i2) & 1u) ? 1.f : 0.f);
                        float cw = wAs + 0.5f * wEs, cv = wAs;
#pragma unroll
                        for (int off = 4; off < 32; off <<= 1) {
                            cw += __shfl_xor_sync(0xffffffffu, cw, off);
                            cv += __shfl_xor_sync(0xffffffffu, cv, off);
                        }
                        if (l < 4) {
                            int col = cb + np * 16 + ((j0i & 4) ? 8 : 0) + 2 * l + (j0i & 1);
                            csum[wr * 768 + 4 * 128 + col] = cw;
                            csum[wr * 768 + 5 * 128 + col] = cv;
                        }
                    }
            }
        } else if (c == 5 || c == 7) {
            // ---- logit epilogue: row side ----
            float sA = 0.f, sB = 0.f, zA = 0.f, zB = 0.f;
#pragma unroll
            for (int np = 0; np < 4; np++)
#pragma unroll
                for (int j = 0; j < 8; j++) {
                    int idx = np * 8 + j;
                    float v = acc[idx];
                    float wgt = (((bA >> idx) & 1u) ? 1.0f : 0.0f) +
                                (((bE >> idx) & 1u) ? 0.5f : 0.0f);
                    float e = ex2f(KE * (v - 1.0f));
                    float za = ((bN >> idx) & 1u) ? e : 0.f;
                    if (j & 2) { sB += wgt * v; zB += za; }
                    else       { sA += wgt * v; zA += za; }
                }
            if (c == 5) { SzA = sA; SzB = sB; ZzA = zA; ZzB = zB; }
            else        { SmA = sA; SmB = sB; ZmA = zA; ZmB = zB; }
            // ---- col side ----
            if (a != b) {
                int q0 = (c == 5) ? 0 : 2;
#pragma unroll
                for (int np = 0; np < 4; np++)
#pragma unroll
                    for (int jc = 0; jc < 4; jc++) {
                        int j0i = (jc & 1) | ((jc & 2) << 1);
                        int i1 = np * 8 + j0i, i2 = i1 + 2;
                        float v1 = acc[i1], v2 = acc[i2];
                        float w1 = (((bA >> i1) & 1u) ? 1.0f : 0.0f) +
                                   (((bE >> i1) & 1u) ? 0.5f : 0.0f);
                        float w2 = (((bA >> i2) & 1u) ? 1.0f : 0.0f) +
                                   (((bE >> i2) & 1u) ? 0.5f : 0.0f);
                        float sv = w1 * v1 + w2 * v2;
                        float e1 = ex2f(KE * (v1 - 1.0f));
                        float e2 = ex2f(KE * (v2 - 1.0f));
                        float ze = (((bNT >> i1) & 1u) ? e1 : 0.f) +
                                   (((bNT >> i2) & 1u) ? e2 : 0.f);
#pragma unroll
                        for (int off = 4; off < 32; off <<= 1) {
                            sv += __shfl_xor_sync(0xffffffffu, sv, off);
                            ze += __shfl_xor_sync(0xffffffffu, ze, off);
                        }
                        if (l < 4) {
                            int col = cb + np * 16 + ((j0i & 4) ? 8 : 0) + 2 * l + (j0i & 1);
                            csum[wr * 768 + q0 * 128 + col] = ze;
                            csum[wr * 768 + (q0 + 1) * 128 + col] = sv;
                        }
                    }
            }
        }

        __syncthreads();
        if (c + 2 < 8) {
            int cc = c + 2;
            const __nv_bfloat16* hi = &g_bf[cc >> 1][0][0];
            const __nv_bfloat16* lo = &g_bf[cc >> 1][1][0];
            int h = cc & 1;
            unsigned bn = sb + (unsigned)(c & 1) * BUF_STRIDE;
            load_tile(bn,              hi, g0, h, tid, 512);
            load_tile(bn + TILE_B,     lo, g0, h, tid, 512);
            load_tile(bn + 2 * TILE_B, hi, j0, h, tid, 512);
            load_tile(bn + 3 * TILE_B, lo, j0, h, tid, 512);
            CP_COMMIT();
        }
    }

    // ---- row-side: reduce over lane cols, write per-col-half partials ----
    float pAa = (float)__popc(bA & 0x33333333u);
    float pAb = (float)__popc(bA & 0xCCCCCCCCu);
    float pEa = (float)__popc(bE & 0x33333333u);
    float pEb = (float)__popc(bE & 0xCCCCCCCCu);
    float qA[6] = {ZzA, ZmA, SzA, SmA, pAa + 0.5f * pEa, pAa};
    float qB[6] = {ZzB, ZmB, SzB, SmB, pAb + 0.5f * pEb, pAb};
#pragma unroll
    for (int q = 0; q < 6; q++) {
#pragma unroll
        for (int off = 1; off < 4; off <<= 1) {
            qA[q] += __shfl_xor_sync(0xffffffffu, qA[q], off);
            qB[q] += __shfl_xor_sync(0xffffffffu, qB[q], off);
        }
    }
    if ((l & 3) == 0) {
#pragma unroll
        for (int q = 0; q < 6; q++) {
            rsum[(wc * 128 + rA) * 6 + q] = qA[q];
            rsum[(wc * 128 + rB) * 6 + q] = qB[q];
        }
    }
    __syncthreads();
    if (tid < 128) {
        float* d = &g_part[b][(size_t)(g0 + tid) * 6];
#pragma unroll
        for (int q = 0; q < 6; q++)
            d[q] = rsum[tid * 6 + q] + rsum[(128 + tid) * 6 + q];
    }

    // ---- col-side write ----
    if (a != b && tid >= 128 && tid < 256) {
        int colx = tid - 128;
        float s[6] = {0.f, 0.f, 0.f, 0.f, 0.f, 0.f};
#pragma unroll
        for (int w8 = 0; w8 < 8; w8++)
#pragma unroll
            for (int q = 0; q < 6; q++) s[q] += csum[w8 * 768 + q * 128 + colx];
        float* d = &g_part[a][(size_t)(j0 + colx) * 6];
        d[0] = s[0];   // Zz
        d[1] = s[2];   // Zm
        d[2] = s[1];   // Sz
        d[3] = s[3];   // Sm
        d[4] = s[4];   // ws
        d[5] = s[5];   // vc
    }
}

// ---------------- slot sum + final reduction ----------------
__global__ void slotsum_kernel() {
    int i = blockIdx.x * 256 + threadIdx.x;
    float s = 0.f;
    for (int sl = 0; sl < NT; sl++) s += g_part[sl][i];
    g_sum[i] = s;
}

__global__ void reduce_kernel(float* __restrict__ out) {
    __shared__ float s1[256], s2[256];
    int tid = threadIdx.x;
    float grand = 0.f;
    for (int m = 0; m < 16; m++) {
        int i = m * 256 + tid;
        float q[6];
#pragma unroll
        for (int qn = 0; qn < 6; qn++) q[qn] = g_sum[(size_t)i * 6 + qn];
        float Zz = q[0], Zm = q[1], Sz = q[2], Sm = q[3], ww = q[4], vcc = q[5];
        float num = 0.f, den = 0.f;
        if (vcc > 0.5f) {
            float lzz = INV_TEMP + LN2 * lg2f(Zz);
            float lzm = INV_TEMP + LN2 * lg2f(Zm);
            num = INV_TEMP * (Sz + Sm) - ww * (lzz + lzm);
            den = ww;
        }
        s1[tid] = num;
        s2[tid] = den;
        __syncthreads();
        for (int off = 128; off > 0; off >>= 1) {
            if (tid < off) { s1[tid] += s1[tid + off]; s2[tid] += s2[tid + off]; }
            __syncthreads();
        }
        if (tid == 0 && s2[0] != 0.f) grand += s1[0] / s2[0];
        __syncthreads();
    }
    if (tid == 0) out[0] = -grand / 32.0f;   // /M/2 with M=16
}

// ---------------- launch ----------------
extern "C" void kernel_launch(void* const* d_in, const int* in_sizes, int n_in,
                              void* d_out, int out_size) {
    const float* z    = (const float*)d_in[0];
    const float* spr  = (const float*)d_in[1];
    const float* f    = (const float*)d_in[2];
    const float* pag  = (const float*)d_in[3];
    const float* psp  = (const float*)d_in[4];
    const float* zmix = (const float*)d_in[5];
    const float* base = (const float*)d_in[6];
    float* out = (float*)d_out;

    const int SMEM_RMAX = 2 * BUF_STRIDE;     // 147456
    cudaFuncSetAttribute(rmax2_kernel, cudaFuncAttributeMaxDynamicSharedMemorySize, SMEM_RMAX);
    cudaFuncSetAttribute(pair_kernel, cudaFuncAttributeMaxDynamicSharedMemorySize, SMEM_PAIR);

    prep_kernel<<<2048, 256>>>(z, spr, f, zmix, pag, psp, base);
    rmax2_kernel<<<dim3(32, 8, 2), 256, SMEM_RMAX>>>();
    merge2_kernel<<<16, 256>>>();
    pair_kernel<<<NPAIR, 512, SMEM_PAIR>>>();
    slotsum_kernel<<<96, 256>>>();
    reduce_kernel<<<1, 256>>>(out);
}